// round 10
// baseline (speedup 1.0000x reference)
#include <cuda_runtime.h>
#include <cuda_bf16.h>
#include <cuda_fp16.h>
#include <math.h>

#define NM 100000
#define ND 20000
#define NA 50000
#define NE 300000
#define CAP 48   // edge bucket capacity per movie node (Poisson(6): P(deg>=48) ~ 1e-30)

// ---------------- device scratch ----------------
__device__ __align__(16) __half d_q0[NM * 128];      // movie Q (fp16)
__device__ __align__(16) float d_preout[NM * 8];     // (1-g)*xs0 @ Wlin (folded, fp32!)
__device__ __align__(16) __half d_kmD[ND * 256];     // director [Ktilde | Mtilde] fp16
__device__ __align__(16) __half d_kmA[NA * 256];     // actor    [Ktilde | Mtilde] fp16
__device__ __align__(16) float d_KeffD[128 * 128];
__device__ __align__(16) float d_MeffD[128 * 128];
__device__ __align__(16) float d_KeffA[128 * 128];
__device__ __align__(16) float d_MeffA[128 * 128];
// W in bf16 split-2 fragment layout: [kchunk16][ntile8][lane(32)][8 bf16 {hi_r0(2),hi_r1(2),lo_r0(2),lo_r1(2)}]
__device__ __align__(16) __nv_bfloat16 d_WM[16 * 20 * 32 * 8];  // K=256, NT=20
__device__ __align__(16) float d_bM[160];
__device__ __align__(16) __nv_bfloat16 d_WD[8 * 32 * 32 * 8];   // K=128, NT=32
__device__ __align__(16) float d_bD[256];
__device__ __align__(16) __nv_bfloat16 d_WA[8 * 32 * 32 * 8];
__device__ __align__(16) float d_bA[256];
__device__ __align__(16) float d_Wfin[128 * 8];
__device__ __align__(16) float d_bfin[8];
// bucketized edges
__device__ int d_cursor[NM];
__device__ unsigned d_edges[(size_t)NM * CAP];

// Write weight value w at (k=i, n=j) into bf16 split fragment layout (NT n-tiles).
__device__ __forceinline__ void frag_write(__nv_bfloat16* Wg, int NT, int i, int j, float w) {
    int kchunk = i >> 4, kin = i & 15;
    int ntile = j >> 3;
    int tig = (kin & 7) >> 1;
    int lane = (j & 7) * 4 + tig;
    int reg = (kin >= 8) ? 1 : 0;
    int half = kin & 1;
    __nv_bfloat16 h = __float2bfloat16_rn(w);
    float lo = w - __bfloat162float(h);
    size_t base = ((size_t)(kchunk * NT + ntile) * 32 + lane) * 8;
    Wg[base + reg * 2 + half] = h;
    Wg[base + 4 + reg * 2 + half] = __float2bfloat16_rn(lo);
}

// ================= phase A: zero cursors + independent folds =================
// grid: [0,391) zero cursors | [391,647) fold_eff | [647,687) fold_M | [687,691) fold_fin
__global__ void __launch_bounds__(256) phaseA_kernel(
    const float* __restrict__ Wk, const float* __restrict__ Wv,
    const float* __restrict__ A, const float* __restrict__ Mm,
    const float* __restrict__ P,
    const float* __restrict__ Wpre_m, const float* __restrict__ Wq,
    const float* __restrict__ Wlin, const float* __restrict__ skip,
    const float* __restrict__ Wa) {
    int b = blockIdx.x;
    if (b < 391) {                                 // ---- zero cursors
        int i = b * 256 + threadIdx.x;
        if (i < NM) d_cursor[i] = 0;
    } else if (b < 647) {                          // ---- fold_eff
        int idx = (b - 391) * 256 + threadIdx.x;
        int mat = idx >> 14, e = idx & 16383;
        int t = e >> 7, c = e & 127, h = c >> 4, f = c & 15;
        const float *W, *T;
        float fac;
        float* outp;
        if (mat == 0)      { W = Wk + 16384; T = A;         fac = P[h] * 0.25f;     outp = d_KeffD; }
        else if (mat == 1) { W = Wv + 16384; T = Mm;        fac = 1.f;              outp = d_MeffD; }
        else if (mat == 2) { W = Wk + 32768; T = A + 2048;  fac = P[8 + h] * 0.25f; outp = d_KeffA; }
        else               { W = Wv + 32768; T = Mm + 2048; fac = 1.f;              outp = d_MeffA; }
        float s = 0.f;
        #pragma unroll
        for (int dd = 0; dd < 16; dd++)
            s += W[t * 128 + h * 16 + dd] * T[h * 256 + dd * 16 + f];
        outp[t * 128 + c] = s * fac;
    } else if (b < 687) {                          // ---- fold_M
        int idx = (b - 647) * 256 + threadIdx.x;   // < 10240
        int i = idx / 40, jq = (idx % 40) * 4;
        float a0 = 0.f, a1 = 0.f, a2 = 0.f, a3 = 0.f;
        if (jq < 128) {
            for (int t = 0; t < 128; t++) {
                float w = Wpre_m[i * 128 + t];
                float4 e = *(const float4*)(Wq + t * 128 + jq);
                a0 = fmaf(w, e.x, a0); a1 = fmaf(w, e.y, a1);
                a2 = fmaf(w, e.z, a2); a3 = fmaf(w, e.w, a3);
            }
        } else if (jq < 136) {
            for (int t = 0; t < 128; t++) {
                float w = Wpre_m[i * 128 + t];
                float4 e = *(const float4*)(Wlin + t * 8 + (jq - 128));
                a0 = fmaf(w, e.x, a0); a1 = fmaf(w, e.y, a1);
                a2 = fmaf(w, e.z, a2); a3 = fmaf(w, e.w, a3);
            }
            float g = 1.f / (1.f + __expf(-skip[0]));
            a0 *= (1.f - g); a1 *= (1.f - g); a2 *= (1.f - g); a3 *= (1.f - g);
        }
        frag_write(d_WM, 20, i, jq + 0, a0);
        frag_write(d_WM, 20, i, jq + 1, a1);
        frag_write(d_WM, 20, i, jq + 2, a2);
        frag_write(d_WM, 20, i, jq + 3, a3);
    } else {                                       // ---- fold_fin
        int idx = (b - 687) * 256 + threadIdx.x;   // < 1024
        int i = idx >> 3, j = idx & 7;
        float g = 1.f / (1.f + __expf(-skip[0]));
        float s = 0.f;
        for (int t = 0; t < 128; t++) s += Wa[i * 128 + t] * Wlin[t * 8 + j];
        d_Wfin[idx] = g * s;
    }
}

// ================= phase B: dependent folds + edge scatter (overlapped) =================
// grid: [0,64) fold_DA | [64,68) fold_bias | [68,361) scatter rel0 | [361,654) scatter rel1
__global__ void __launch_bounds__(256) phaseB_kernel(
    const float* __restrict__ Wpre_d, const float* __restrict__ Wpre_a,
    const float* __restrict__ bpre, const float* __restrict__ bq,
    const float* __restrict__ bk, const float* __restrict__ bv,
    const float* __restrict__ Wq, const float* __restrict__ Wlin,
    const float* __restrict__ A, const float* __restrict__ Mm,
    const float* __restrict__ P, const float* __restrict__ skip,
    const float* __restrict__ ba, const float* __restrict__ blin,
    const int* __restrict__ src_dm, const int* __restrict__ dst_dm,
    const int* __restrict__ src_am, const int* __restrict__ dst_am) {
    int b = blockIdx.x;
    if (b < 64) {                                  // ---- fold_DA
        int sel = (b >= 32);
        int idx = (b & 31) * 256 + threadIdx.x;    // < 8192
        int i = idx >> 6, jq = (idx & 63) * 4;
        const float* Wpre = sel ? Wpre_a : Wpre_d;
        const float* Keff = sel ? d_KeffA : d_KeffD;
        const float* Meff = sel ? d_MeffA : d_MeffD;
        const float* Eff = (jq < 128) ? Keff : Meff;
        int jj = jq & 127;
        float a0 = 0.f, a1 = 0.f, a2 = 0.f, a3 = 0.f;
        for (int t = 0; t < 128; t++) {
            float w = Wpre[i * 128 + t];
            float4 e = *(const float4*)(Eff + t * 128 + jj);
            a0 = fmaf(w, e.x, a0); a1 = fmaf(w, e.y, a1);
            a2 = fmaf(w, e.z, a2); a3 = fmaf(w, e.w, a3);
        }
        __nv_bfloat16* Wg = sel ? d_WA : d_WD;
        frag_write(Wg, 32, i, jq + 0, a0);
        frag_write(Wg, 32, i, jq + 1, a1);
        frag_write(Wg, 32, i, jq + 2, a2);
        frag_write(Wg, 32, i, jq + 3, a3);
    } else if (b < 68) {                           // ---- fold_bias
        int tid = (b - 64) * 256 + threadIdx.x;    // < 1024
        float g = 1.f / (1.f + __expf(-skip[0]));
        if (tid < 160) {
            int j = tid;
            float s = 0.f;
            if (j < 128) {
                for (int t = 0; t < 128; t++) s += bpre[t] * Wq[t * 128 + j];
                s += bq[j];
            } else if (j < 136) {
                int jj = j - 128;
                for (int t = 0; t < 128; t++) s += bpre[t] * Wlin[t * 8 + jj];
                s *= (1.f - g);
            }
            d_bM[j] = s;
        } else if (tid < 672) {
            int u = tid - 160;
            int sel = u >> 8;
            int j = u & 255;
            const float* bpre_r = bpre + (sel ? 256 : 128);
            const float* Keff = sel ? d_KeffA : d_KeffD;
            const float* Meff = sel ? d_MeffA : d_MeffD;
            int jj = j & 127, h = jj >> 4, f = jj & 15;
            float s = 0.f;
            if (j < 128) {
                for (int t = 0; t < 128; t++) s += bpre_r[t] * Keff[t * 128 + jj];
                const float* bkr = bk + (sel ? 256 : 128);
                const float* Ar = A + (sel ? 2048 : 0);
                float fac = P[sel * 8 + h] * 0.25f;
                float s2 = 0.f;
                #pragma unroll
                for (int dd = 0; dd < 16; dd++) s2 += bkr[h * 16 + dd] * Ar[h * 256 + dd * 16 + f];
                s += s2 * fac;
            } else {
                for (int t = 0; t < 128; t++) s += bpre_r[t] * Meff[t * 128 + jj];
                const float* bvr = bv + (sel ? 256 : 128);
                const float* Mr = Mm + (sel ? 2048 : 0);
                float s2 = 0.f;
                #pragma unroll
                for (int dd = 0; dd < 16; dd++) s2 += bvr[h * 16 + dd] * Mr[h * 256 + dd * 16 + f];
                s += s2;
            }
            if (sel) d_bA[j] = s; else d_bD[j] = s;
        } else if (tid < 680) {
            int j = tid - 672;
            float s = 0.f;
            for (int t = 0; t < 128; t++) s += ba[t] * Wlin[t * 8 + j];
            d_bfin[j] = g * s + blin[j];
        }
    } else {                                       // ---- edge scatter (4 edges/thread, int4)
        int t = b - 68;
        int rel = (t >= 293);
        t -= rel * 293;
        int e4 = t * 256 + threadIdx.x;
        if (e4 >= NE / 4) return;
        const int* srcp = rel ? src_am : src_dm;
        const int* dstp = rel ? dst_am : dst_dm;
        int4 s4 = ((const int4*)srcp)[e4];
        int4 dd4 = ((const int4*)dstp)[e4];
        unsigned rbit = (unsigned)rel << 31;
        int ss[4] = {s4.x, s4.y, s4.z, s4.w};
        int dd[4] = {dd4.x, dd4.y, dd4.z, dd4.w};
        #pragma unroll
        for (int u = 0; u < 4; u++) {
            int pos = atomicAdd(&d_cursor[dd[u]], 1);
            if (pos < CAP)
                d_edges[(size_t)dd[u] * CAP + pos] = (unsigned)ss[u] | rbit;
        }
    }
}

// ---------------- bf16 m16n8k16 mma ----------------
__device__ __forceinline__ void mma16(float4& c, const unsigned* a, unsigned b0, unsigned b1) {
    asm volatile(
        "mma.sync.aligned.m16n8k16.row.col.f32.bf16.bf16.f32 "
        "{%0,%1,%2,%3}, {%4,%5,%6,%7}, {%8,%9}, {%0,%1,%2,%3};"
        : "+f"(c.x), "+f"(c.y), "+f"(c.z), "+f"(c.w)
        : "r"(a[0]), "r"(a[1]), "r"(a[2]), "r"(a[3]), "r"(b0), "r"(b1));
}
__device__ __forceinline__ void split2(float2 v, unsigned& hi, unsigned& lo) {
    __nv_bfloat162 hp = __float22bfloat162_rn(v);
    float2 hf = __bfloat1622float2(hp);
    float2 lf = make_float2(v.x - hf.x, v.y - hf.y);
    __nv_bfloat162 lp = __float22bfloat162_rn(lf);
    hi = *(unsigned*)&hp;
    lo = *(unsigned*)&lp;
}

// ---------------- tensor-core GEMM body: W staged ONCE, RB row-blocks per CTA ----------------
// acc = Ahi*Whi + Ahi*Wlo + Alo*Whi  (3 mma passes, split-compensated bf16; rel_err ~5e-6)
// 512 thr, 16 warps (8 row x 2 col), 128 rows per row-block.
template<int K, int NT, int MODE, int RB>
__device__ __forceinline__ void gemm_body(const float* __restrict__ Ag, int N, int bid,
                                          char* shraw) {
    constexpr int CH = K / 16;
    constexpr int NTW = NT / 2;
    uint4* Ws = (uint4*)shraw;                     // CH*NT*32 uint4
    const uint4* Wg = (const uint4*)((MODE == 0) ? (const void*)d_WM
                                  : (MODE == 1) ? (const void*)d_WD : (const void*)d_WA);
    const float* bg = (MODE == 0) ? d_bM : (MODE == 1) ? d_bD : d_bA;

    int tid = threadIdx.x, warp = tid >> 5, lane = tid & 31;
    int wr = warp >> 1, wc = warp & 1;
    int g = lane >> 2, tig = lane & 3;

    for (int i = tid; i < CH * NT * 32; i += 512) Ws[i] = Wg[i];
    __syncthreads();

    for (int rb = 0; rb < RB; rb++) {
        int r0 = (bid * RB + rb) * 128;
        int rbase = r0 + wr * 16 + g;
        bool va = rbase < N, vb = (rbase + 8) < N;
        const float* pa = Ag + (size_t)rbase * K;
        const float* pb = Ag + (size_t)(rbase + 8) * K;
        float2 z = make_float2(0.f, 0.f);

        float2 cur[4], nxt[4];
        cur[0] = va ? *(const float2*)(pa + tig * 2) : z;
        cur[1] = vb ? *(const float2*)(pb + tig * 2) : z;
        cur[2] = va ? *(const float2*)(pa + 8 + tig * 2) : z;
        cur[3] = vb ? *(const float2*)(pb + 8 + tig * 2) : z;

        float4 acc[NTW];
        #pragma unroll
        for (int t = 0; t < NTW; t++) acc[t] = make_float4(0.f, 0.f, 0.f, 0.f);

        for (int c = 0; c < CH; c++) {
            if (c + 1 < CH) {
                int kb = (c + 1) * 16;
                nxt[0] = va ? *(const float2*)(pa + kb + tig * 2) : z;
                nxt[1] = vb ? *(const float2*)(pb + kb + tig * 2) : z;
                nxt[2] = va ? *(const float2*)(pa + kb + 8 + tig * 2) : z;
                nxt[3] = vb ? *(const float2*)(pb + kb + 8 + tig * 2) : z;
            }
            unsigned ah[4], al[4];
            split2(cur[0], ah[0], al[0]);
            split2(cur[1], ah[1], al[1]);
            split2(cur[2], ah[2], al[2]);
            split2(cur[3], ah[3], al[3]);
            const uint4* wrow = Ws + c * NT * 32 + lane;
            #pragma unroll
            for (int t = 0; t < NTW; t++) {
                uint4 bfrag = wrow[(wc + 2 * t) * 32];
                mma16(acc[t], ah, bfrag.x, bfrag.y);   // hi*Whi
                mma16(acc[t], ah, bfrag.z, bfrag.w);   // hi*Wlo
                mma16(acc[t], al, bfrag.x, bfrag.y);   // lo*Whi
            }
            #pragma unroll
            for (int u = 0; u < 4; u++) cur[u] = nxt[u];
        }

        int row0 = r0 + wr * 16 + g;
        #pragma unroll
        for (int t = 0; t < NTW; t++) {
            int col = (wc + 2 * t) * 8 + tig * 2;       // always even
            float2 bb = make_float2(bg[col], bg[col + 1]);
            #pragma unroll
            for (int u = 0; u < 2; u++) {
                int row = row0 + u * 8;
                if (row >= N) continue;
                float vx = (u ? acc[t].z : acc[t].x) + bb.x;
                float vy = (u ? acc[t].w : acc[t].y) + bb.y;
                if (MODE == 0) {
                    if (col < 128)
                        ((half2*)d_q0)[(size_t)row * 64 + (col >> 1)] = __floats2half2_rn(vx, vy);
                    else if (col < 136)
                        *(float2*)(d_preout + (size_t)row * 8 + (col - 128)) = make_float2(vx, vy);
                } else if (MODE == 1) {
                    ((half2*)d_kmD)[(size_t)row * 128 + (col >> 1)] = __floats2half2_rn(vx, vy);
                } else {
                    ((half2*)d_kmA)[(size_t)row * 128 + (col >> 1)] = __floats2half2_rn(vx, vy);
                }
            }
        }
    }
}

// one launch, all three GEMMs (RB=2): [0,391) movie | [391,470) director | [470,666) actor
__global__ void __launch_bounds__(512) gemm_all(const float* __restrict__ xm,
                                                const float* __restrict__ xd,
                                                const float* __restrict__ xa) {
    extern __shared__ char sh[];
    int b = blockIdx.x;
    if (b < 391)       gemm_body<256, 20, 0, 2>(xm, NM, b, sh);
    else if (b < 470)  gemm_body<128, 32, 1, 2>(xd, ND, b - 391, sh);
    else               gemm_body<128, 32, 2, 2>(xa, NA, b - 470, sh);
}

// ---------------- fused aggregate + gelu + head: one warp per movie node ----------------
// Batched prefetch: all kv/mv loads for up to 8 edges issued before any compute (MLP ~16).
__device__ __forceinline__ float4 h4_to_f4(uint2 r) {
    float2 a = __half22float2(*(half2*)&r.x);
    float2 b = __half22float2(*(half2*)&r.y);
    return make_float4(a.x, a.y, b.x, b.y);
}

__global__ void __launch_bounds__(256) agg_final(float* __restrict__ out) {
    int w = (blockIdx.x * blockDim.x + threadIdx.x) >> 5;
    int lane = threadIdx.x & 31;
    if (w >= NM) return;
    float4 qv = h4_to_f4(((const uint2*)d_q0)[(size_t)w * 32 + lane]);
    int deg = min(d_cursor[w], CAP);
    const unsigned* ep = d_edges + (size_t)w * CAP;
    float4 acc = make_float4(0.f, 0.f, 0.f, 0.f);
    float den = 0.f;

    for (int base = 0; base < deg; base += 8) {
        int m = min(8, deg - base);              // warp-uniform
        uint2 kr[8], mr[8];
        #pragma unroll
        for (int j = 0; j < 8; j++) {
            if (j < m) {
                unsigned pk = ep[base + j];
                const uint2* km = (pk >> 31) ? (const uint2*)d_kmA : (const uint2*)d_kmD;
                size_t s = pk & 0x7fffffffu;
                kr[j] = km[s * 64 + lane];
                mr[j] = km[s * 64 + 32 + lane];
            }
        }
        #pragma unroll
        for (int j = 0; j < 8; j++) {
            if (j < m) {
                float4 kv = h4_to_f4(kr[j]);
                float4 mv = h4_to_f4(mr[j]);
                float p = qv.x * kv.x + qv.y * kv.y + qv.z * kv.z + qv.w * kv.w;
                p += __shfl_xor_sync(0xffffffffu, p, 1);
                p += __shfl_xor_sync(0xffffffffu, p, 2);   // per-head dot (4 lanes)
                float wgt = __expf(p);
                acc.x = fmaf(wgt, mv.x, acc.x);
                acc.y = fmaf(wgt, mv.y, acc.y);
                acc.z = fmaf(wgt, mv.z, acc.z);
                acc.w = fmaf(wgt, mv.w, acc.w);
                den += wgt;
            }
        }
    }

    float inv = 1.f / fmaxf(den, 1e-16f);
    float gx[4] = {acc.x * inv, acc.y * inv, acc.z * inv, acc.w * inv};
    #pragma unroll
    for (int c = 0; c < 4; c++)
        gx[c] = 0.5f * gx[c] * (1.f + erff(gx[c] * 0.70710678118654752f));
    float p[8];
    #pragma unroll
    for (int j = 0; j < 8; j++) p[j] = 0.f;
    #pragma unroll
    for (int c = 0; c < 4; c++) {
        #pragma unroll
        for (int j = 0; j < 8; j++)
            p[j] = fmaf(gx[c], d_Wfin[(lane * 4 + c) * 8 + j], p[j]);
    }
    #pragma unroll
    for (int off = 16; off > 0; off >>= 1)
        #pragma unroll
        for (int j = 0; j < 8; j++)
            p[j] += __shfl_xor_sync(0xffffffffu, p[j], off);
    if (lane == 0) {
        #pragma unroll
        for (int j = 0; j < 8; j++)
            out[w * 8 + j] = p[j] + d_preout[w * 8 + j] + d_bfin[j];
    }
}

// ---------------- launch ----------------
extern "C" void kernel_launch(void* const* d_in, const int* in_sizes, int n_in,
                              void* d_out, int out_size) {
    const float* x_movie = (const float*)d_in[0];
    const float* x_dir   = (const float*)d_in[1];
    const float* x_act   = (const float*)d_in[2];
    const int* src_dm = (const int*)d_in[3];
    const int* dst_dm = (const int*)d_in[4];
    const int* src_am = (const int*)d_in[5];
    const int* dst_am = (const int*)d_in[6];
    // d_in[7..10] dead (only movie output matters)
    const float* Wpre_m = (const float*)d_in[11];
    const float* Wpre_d = (const float*)d_in[12];
    const float* Wpre_a = (const float*)d_in[13];
    const float* bpre = (const float*)d_in[14];
    const float* Wk   = (const float*)d_in[15];
    const float* bk   = (const float*)d_in[16];
    const float* Wq   = (const float*)d_in[17];
    const float* bq   = (const float*)d_in[18];
    const float* Wv   = (const float*)d_in[19];
    const float* bv   = (const float*)d_in[20];
    const float* a_rel = (const float*)d_in[21];
    const float* m_rel = (const float*)d_in[22];
    const float* p_rel = (const float*)d_in[23];
    const float* skip  = (const float*)d_in[24];
    const float* Wa    = (const float*)d_in[25];
    const float* ba    = (const float*)d_in[26];
    const float* Wlin  = (const float*)d_in[27];
    const float* blin  = (const float*)d_in[28];
    float* out = (float*)d_out;

    const int smemG = 16 * 20 * 32 * 16;   // 163840 (movie split-W, max of the three)
    cudaFuncSetAttribute(gemm_all, cudaFuncAttributeMaxDynamicSharedMemorySize, smemG);

    phaseA_kernel<<<691, 256>>>(Wk, Wv, a_rel, m_rel, p_rel, Wpre_m, Wq, Wlin, skip, Wa);
    phaseB_kernel<<<654, 256>>>(Wpre_d, Wpre_a, bpre, bq, bk, bv, Wq, Wlin,
                                a_rel, m_rel, p_rel, skip, ba, blin,
                                src_dm, dst_dm, src_am, dst_am);
    gemm_all<<<666, 512, smemG>>>(x_movie, x_dir, x_act);
    agg_final<<<(NM * 32 + 255) / 256, 256>>>(out);
}

// round 17
// speedup vs baseline: 1.2714x; 1.2714x over previous
#include <cuda_runtime.h>
#include <cuda_fp16.h>
#include <cstdint>
#include <math.h>

#define NM 100000
#define ND 20000
#define NA 50000
#define NE 300000
#define CAP 48   // edge bucket capacity per movie node (Poisson(6): P(deg>=48) ~ 1e-30)

// ---------------- device scratch ----------------
__device__ __align__(16) __half d_q0[NM * 128];      // movie Q (fp16)
__device__ __align__(16) float d_preout[NM * 8];     // (1-g)*xs0 @ Wlin (folded, fp32!)
__device__ __align__(16) __half d_kmD[ND * 256];     // director [Ktilde | Mtilde] fp16
__device__ __align__(16) __half d_kmA[NA * 256];     // actor    [Ktilde | Mtilde] fp16
__device__ __align__(16) float d_KeffD[128 * 128];
__device__ __align__(16) float d_MeffD[128 * 128];
__device__ __align__(16) float d_KeffA[128 * 128];
__device__ __align__(16) float d_MeffA[128 * 128];
// W in fp16 mma fragment layout: [kchunk16][ntile8][lane(32)][4 fp16 {b0(2), b1(2)}]
__device__ __align__(16) __half d_WM[16 * 20 * 32 * 4];  // K=256, NT=20 (160 cols)
__device__ __align__(16) float d_bM[160];
__device__ __align__(16) __half d_WD[8 * 32 * 32 * 4];   // K=128, NT=32 (256 cols)
__device__ __align__(16) float d_bD[256];
__device__ __align__(16) __half d_WA[8 * 32 * 32 * 4];
__device__ __align__(16) float d_bA[256];
__device__ __align__(16) float d_Wfin[128 * 8];
__device__ __align__(16) float d_bfin[8];
// bucketized edges
__device__ int d_cursor[NM];
__device__ unsigned d_edges[(size_t)NM * CAP];

// Write weight value w (fp16) at (k=i, n=j) into fragment layout (NT n-tiles).
__device__ __forceinline__ void frag_write(__half* Wg, int NT, int i, int j, float w) {
    int kchunk = i >> 4, kin = i & 15;
    int ntile = j >> 3;
    int tig = (kin & 7) >> 1;
    int lane = (j & 7) * 4 + tig;
    int reg = (kin >= 8) ? 1 : 0;
    int half_ = kin & 1;
    size_t base = ((size_t)(kchunk * NT + ntile) * 32 + lane) * 4;
    Wg[base + reg * 2 + half_] = __float2half_rn(w);
}

// ================= phase A: zero cursors + independent folds =================
// grid: [0,391) zero cursors | [391,647) fold_eff | [647,687) fold_M | [687,691) fold_fin
__global__ void __launch_bounds__(256) phaseA_kernel(
    const float* __restrict__ Wk, const float* __restrict__ Wv,
    const float* __restrict__ A, const float* __restrict__ Mm,
    const float* __restrict__ P,
    const float* __restrict__ Wpre_m, const float* __restrict__ Wq,
    const float* __restrict__ Wlin, const float* __restrict__ skip,
    const float* __restrict__ Wa) {
    int b = blockIdx.x;
    if (b < 391) {                                 // ---- zero cursors
        int i = b * 256 + threadIdx.x;
        if (i < NM) d_cursor[i] = 0;
    } else if (b < 647) {                          // ---- fold_eff
        int idx = (b - 391) * 256 + threadIdx.x;
        int mat = idx >> 14, e = idx & 16383;
        int t = e >> 7, c = e & 127, h = c >> 4, f = c & 15;
        const float *W, *T;
        float fac;
        float* outp;
        if (mat == 0)      { W = Wk + 16384; T = A;         fac = P[h] * 0.25f;     outp = d_KeffD; }
        else if (mat == 1) { W = Wv + 16384; T = Mm;        fac = 1.f;              outp = d_MeffD; }
        else if (mat == 2) { W = Wk + 32768; T = A + 2048;  fac = P[8 + h] * 0.25f; outp = d_KeffA; }
        else               { W = Wv + 32768; T = Mm + 2048; fac = 1.f;              outp = d_MeffA; }
        float s = 0.f;
        #pragma unroll
        for (int dd = 0; dd < 16; dd++)
            s += W[t * 128 + h * 16 + dd] * T[h * 256 + dd * 16 + f];
        outp[t * 128 + c] = s * fac;
    } else if (b < 687) {                          // ---- fold_M
        int idx = (b - 647) * 256 + threadIdx.x;   // < 10240
        int i = idx / 40, jq = (idx % 40) * 4;
        float a0 = 0.f, a1 = 0.f, a2 = 0.f, a3 = 0.f;
        if (jq < 128) {
            for (int t = 0; t < 128; t++) {
                float w = Wpre_m[i * 128 + t];
                float4 e = *(const float4*)(Wq + t * 128 + jq);
                a0 = fmaf(w, e.x, a0); a1 = fmaf(w, e.y, a1);
                a2 = fmaf(w, e.z, a2); a3 = fmaf(w, e.w, a3);
            }
        } else if (jq < 136) {
            for (int t = 0; t < 128; t++) {
                float w = Wpre_m[i * 128 + t];
                float4 e = *(const float4*)(Wlin + t * 8 + (jq - 128));
                a0 = fmaf(w, e.x, a0); a1 = fmaf(w, e.y, a1);
                a2 = fmaf(w, e.z, a2); a3 = fmaf(w, e.w, a3);
            }
            float g = 1.f / (1.f + __expf(-skip[0]));
            a0 *= (1.f - g); a1 *= (1.f - g); a2 *= (1.f - g); a3 *= (1.f - g);
        }
        frag_write(d_WM, 20, i, jq + 0, a0);
        frag_write(d_WM, 20, i, jq + 1, a1);
        frag_write(d_WM, 20, i, jq + 2, a2);
        frag_write(d_WM, 20, i, jq + 3, a3);
    } else {                                       // ---- fold_fin
        int idx = (b - 687) * 256 + threadIdx.x;   // < 1024
        int i = idx >> 3, j = idx & 7;
        float g = 1.f / (1.f + __expf(-skip[0]));
        float s = 0.f;
        for (int t = 0; t < 128; t++) s += Wa[i * 128 + t] * Wlin[t * 8 + j];
        d_Wfin[idx] = g * s;
    }
}

// ================= phase B: dependent folds + edge scatter (overlapped) =================
// grid: [0,64) fold_DA | [64,68) fold_bias | [68,361) scatter rel0 | [361,654) scatter rel1
__global__ void __launch_bounds__(256) phaseB_kernel(
    const float* __restrict__ Wpre_d, const float* __restrict__ Wpre_a,
    const float* __restrict__ bpre, const float* __restrict__ bq,
    const float* __restrict__ bk, const float* __restrict__ bv,
    const float* __restrict__ Wq, const float* __restrict__ Wlin,
    const float* __restrict__ A, const float* __restrict__ Mm,
    const float* __restrict__ P, const float* __restrict__ skip,
    const float* __restrict__ ba, const float* __restrict__ blin,
    const int* __restrict__ src_dm, const int* __restrict__ dst_dm,
    const int* __restrict__ src_am, const int* __restrict__ dst_am) {
    int b = blockIdx.x;
    if (b < 64) {                                  // ---- fold_DA
        int sel = (b >= 32);
        int idx = (b & 31) * 256 + threadIdx.x;    // < 8192
        int i = idx >> 6, jq = (idx & 63) * 4;
        const float* Wpre = sel ? Wpre_a : Wpre_d;
        const float* Keff = sel ? d_KeffA : d_KeffD;
        const float* Meff = sel ? d_MeffA : d_MeffD;
        const float* Eff = (jq < 128) ? Keff : Meff;
        int jj = jq & 127;
        float a0 = 0.f, a1 = 0.f, a2 = 0.f, a3 = 0.f;
        for (int t = 0; t < 128; t++) {
            float w = Wpre[i * 128 + t];
            float4 e = *(const float4*)(Eff + t * 128 + jj);
            a0 = fmaf(w, e.x, a0); a1 = fmaf(w, e.y, a1);
            a2 = fmaf(w, e.z, a2); a3 = fmaf(w, e.w, a3);
        }
        __half* Wg = sel ? d_WA : d_WD;
        frag_write(Wg, 32, i, jq + 0, a0);
        frag_write(Wg, 32, i, jq + 1, a1);
        frag_write(Wg, 32, i, jq + 2, a2);
        frag_write(Wg, 32, i, jq + 3, a3);
    } else if (b < 68) {                           // ---- fold_bias
        int tid = (b - 64) * 256 + threadIdx.x;    // < 1024
        float g = 1.f / (1.f + __expf(-skip[0]));
        if (tid < 160) {
            int j = tid;
            float s = 0.f;
            if (j < 128) {
                for (int t = 0; t < 128; t++) s += bpre[t] * Wq[t * 128 + j];
                s += bq[j];
            } else if (j < 136) {
                int jj = j - 128;
                for (int t = 0; t < 128; t++) s += bpre[t] * Wlin[t * 8 + jj];
                s *= (1.f - g);
            }
            d_bM[j] = s;
        } else if (tid < 672) {
            int u = tid - 160;
            int sel = u >> 8;
            int j = u & 255;
            const float* bpre_r = bpre + (sel ? 256 : 128);
            const float* Keff = sel ? d_KeffA : d_KeffD;
            const float* Meff = sel ? d_MeffA : d_MeffD;
            int jj = j & 127, h = jj >> 4, f = jj & 15;
            float s = 0.f;
            if (j < 128) {
                for (int t = 0; t < 128; t++) s += bpre_r[t] * Keff[t * 128 + jj];
                const float* bkr = bk + (sel ? 256 : 128);
                const float* Ar = A + (sel ? 2048 : 0);
                float fac = P[sel * 8 + h] * 0.25f;
                float s2 = 0.f;
                #pragma unroll
                for (int dd = 0; dd < 16; dd++) s2 += bkr[h * 16 + dd] * Ar[h * 256 + dd * 16 + f];
                s += s2 * fac;
            } else {
                for (int t = 0; t < 128; t++) s += bpre_r[t] * Meff[t * 128 + jj];
                const float* bvr = bv + (sel ? 256 : 128);
                const float* Mr = Mm + (sel ? 2048 : 0);
                float s2 = 0.f;
                #pragma unroll
                for (int dd = 0; dd < 16; dd++) s2 += bvr[h * 16 + dd] * Mr[h * 256 + dd * 16 + f];
                s += s2;
            }
            if (sel) d_bA[j] = s; else d_bD[j] = s;
        } else if (tid < 680) {
            int j = tid - 672;
            float s = 0.f;
            for (int t = 0; t < 128; t++) s += ba[t] * Wlin[t * 8 + j];
            d_bfin[j] = g * s + blin[j];
        }
    } else {                                       // ---- edge scatter (4 edges/thread, int4)
        int t = b - 68;
        int rel = (t >= 293);
        t -= rel * 293;
        int e4 = t * 256 + threadIdx.x;
        if (e4 >= NE / 4) return;
        const int* srcp = rel ? src_am : src_dm;
        const int* dstp = rel ? dst_am : dst_dm;
        int4 s4 = ((const int4*)srcp)[e4];
        int4 dd4 = ((const int4*)dstp)[e4];
        unsigned rbit = (unsigned)rel << 31;
        int ss[4] = {s4.x, s4.y, s4.z, s4.w};
        int dd[4] = {dd4.x, dd4.y, dd4.z, dd4.w};
        #pragma unroll
        for (int u = 0; u < 4; u++) {
            int pos = atomicAdd(&d_cursor[dd[u]], 1);
            if (pos < CAP)
                d_edges[(size_t)dd[u] * CAP + pos] = (unsigned)ss[u] | rbit;
        }
    }
}

// ---------------- fp16 m16n8k16 mma ----------------
__device__ __forceinline__ void mma16(float4& c, const unsigned* a, unsigned b0, unsigned b1) {
    asm volatile(
        "mma.sync.aligned.m16n8k16.row.col.f32.f16.f16.f32 "
        "{%0,%1,%2,%3}, {%4,%5,%6,%7}, {%8,%9}, {%0,%1,%2,%3};"
        : "+f"(c.x), "+f"(c.y), "+f"(c.z), "+f"(c.w)
        : "r"(a[0]), "r"(a[1]), "r"(a[2]), "r"(a[3]), "r"(b0), "r"(b1));
}
__device__ __forceinline__ unsigned f2h2(float2 v) {
    __half2 h = __floats2half2_rn(v.x, v.y);
    return *(unsigned*)&h;
}

// ---------------- tensor-core GEMM body: W staged ONCE (fp16), RB row-blocks per CTA ----------------
// acc = fp16(A) @ fp16(W)  -- single mma pass; rel_err ~3e-4 (R7-calibrated model).
// 512 thr, 16 warps (8 row x 2 col), 128 rows per row-block.
template<int K, int NT, int MODE, int RB>
__device__ __forceinline__ void gemm_body(const float* __restrict__ Ag, int N, int bid,
                                          char* shraw) {
    constexpr int CH = K / 16;
    constexpr int NTW = NT / 2;
    uint2* Ws = (uint2*)shraw;                     // CH*NT*32 uint2
    const uint4* Wg = (const uint4*)((MODE == 0) ? (const void*)d_WM
                                  : (MODE == 1) ? (const void*)d_WD : (const void*)d_WA);
    const float* bg = (MODE == 0) ? d_bM : (MODE == 1) ? d_bD : d_bA;

    int tid = threadIdx.x, warp = tid >> 5, lane = tid & 31;
    int wr = warp >> 1, wc = warp & 1;
    int g = lane >> 2, tig = lane & 3;

    for (int i = tid; i < CH * NT * 16; i += 512) ((uint4*)Ws)[i] = Wg[i];
    __syncthreads();

    for (int rb = 0; rb < RB; rb++) {
        int r0 = (bid * RB + rb) * 128;
        int rbase = r0 + wr * 16 + g;
        bool va = rbase < N, vb = (rbase + 8) < N;
        const float* pa = Ag + (size_t)rbase * K;
        const float* pb = Ag + (size_t)(rbase + 8) * K;
        float2 z = make_float2(0.f, 0.f);

        float2 cur[4], nxt[4];
        cur[0] = va ? *(const float2*)(pa + tig * 2) : z;
        cur[1] = vb ? *(const float2*)(pb + tig * 2) : z;
        cur[2] = va ? *(const float2*)(pa + 8 + tig * 2) : z;
        cur[3] = vb ? *(const float2*)(pb + 8 + tig * 2) : z;

        float4 acc[NTW];
        #pragma unroll
        for (int t = 0; t < NTW; t++) acc[t] = make_float4(0.f, 0.f, 0.f, 0.f);

        for (int c = 0; c < CH; c++) {
            if (c + 1 < CH) {
                int kb = (c + 1) * 16;
                nxt[0] = va ? *(const float2*)(pa + kb + tig * 2) : z;
                nxt[1] = vb ? *(const float2*)(pb + kb + tig * 2) : z;
                nxt[2] = va ? *(const float2*)(pa + kb + 8 + tig * 2) : z;
                nxt[3] = vb ? *(const float2*)(pb + kb + 8 + tig * 2) : z;
            }
            unsigned ah[4];
            ah[0] = f2h2(cur[0]);
            ah[1] = f2h2(cur[1]);
            ah[2] = f2h2(cur[2]);
            ah[3] = f2h2(cur[3]);
            const uint2* wrow = Ws + c * NT * 32 + lane;
            #pragma unroll
            for (int t = 0; t < NTW; t++) {
                uint2 bfrag = wrow[(wc + 2 * t) * 32];
                mma16(acc[t], ah, bfrag.x, bfrag.y);
            }
            #pragma unroll
            for (int u = 0; u < 4; u++) cur[u] = nxt[u];
        }

        int row0 = r0 + wr * 16 + g;
        #pragma unroll
        for (int t = 0; t < NTW; t++) {
            int col = (wc + 2 * t) * 8 + tig * 2;       // always even
            float2 bb = make_float2(bg[col], bg[col + 1]);
            #pragma unroll
            for (int u = 0; u < 2; u++) {
                int row = row0 + u * 8;
                if (row >= N) continue;
                float vx = (u ? acc[t].z : acc[t].x) + bb.x;
                float vy = (u ? acc[t].w : acc[t].y) + bb.y;
                if (MODE == 0) {
                    if (col < 128)
                        ((half2*)d_q0)[(size_t)row * 64 + (col >> 1)] = __floats2half2_rn(vx, vy);
                    else if (col < 136)
                        *(float2*)(d_preout + (size_t)row * 8 + (col - 128)) = make_float2(vx, vy);
                } else if (MODE == 1) {
                    ((half2*)d_kmD)[(size_t)row * 128 + (col >> 1)] = __floats2half2_rn(vx, vy);
                } else {
                    ((half2*)d_kmA)[(size_t)row * 128 + (col >> 1)] = __floats2half2_rn(vx, vy);
                }
            }
        }
    }
}

// one launch, all three GEMMs (RB=2): [0,391) movie | [391,470) director | [470,666) actor
__global__ void __launch_bounds__(512) gemm_all(const float* __restrict__ xm,
                                                const float* __restrict__ xd,
                                                const float* __restrict__ xa) {
    extern __shared__ char sh[];
    int b = blockIdx.x;
    if (b < 391)       gemm_body<256, 20, 0, 2>(xm, NM, b, sh);
    else if (b < 470)  gemm_body<128, 32, 1, 2>(xd, ND, b - 391, sh);
    else               gemm_body<128, 32, 2, 2>(xa, NA, b - 470, sh);
}

// ---------------- fused aggregate + gelu + head (R9 version: prefetch-1) ----------------
__device__ __forceinline__ float4 h4_to_f4(uint2 r) {
    float2 a = __half22float2(*(half2*)&r.x);
    float2 b = __half22float2(*(half2*)&r.y);
    return make_float4(a.x, a.y, b.x, b.y);
}

__global__ void __launch_bounds__(256) agg_final(float* __restrict__ out) {
    int w = (blockIdx.x * blockDim.x + threadIdx.x) >> 5;
    int lane = threadIdx.x & 31;
    if (w >= NM) return;
    float4 qv = h4_to_f4(((const uint2*)d_q0)[(size_t)w * 32 + lane]);
    int deg = min(d_cursor[w], CAP);
    const unsigned* ep = d_edges + (size_t)w * CAP;
    float4 acc = make_float4(0.f, 0.f, 0.f, 0.f);
    float den = 0.f;
    uint2 kraw = make_uint2(0u, 0u), mraw = make_uint2(0u, 0u);
    if (deg > 0) {
        unsigned pk = ep[0];
        const uint2* km = (pk >> 31) ? (const uint2*)d_kmA : (const uint2*)d_kmD;
        size_t s = pk & 0x7fffffffu;
        kraw = km[s * 64 + lane];
        mraw = km[s * 64 + 32 + lane];
    }
    for (int j = 0; j < deg; j++) {
        uint2 kc = kraw, mc = mraw;
        if (j + 1 < deg) {                       // prefetch next edge
            unsigned pk = ep[j + 1];
            const uint2* km = (pk >> 31) ? (const uint2*)d_kmA : (const uint2*)d_kmD;
            size_t s = pk & 0x7fffffffu;
            kraw = km[s * 64 + lane];
            mraw = km[s * 64 + 32 + lane];
        }
        float4 kv = h4_to_f4(kc);
        float4 mv = h4_to_f4(mc);
        float p = qv.x * kv.x + qv.y * kv.y + qv.z * kv.z + qv.w * kv.w;
        p += __shfl_xor_sync(0xffffffffu, p, 1);
        p += __shfl_xor_sync(0xffffffffu, p, 2);   // per-head dot (4 lanes)
        float wgt = __expf(p);
        acc.x = fmaf(wgt, mv.x, acc.x);
        acc.y = fmaf(wgt, mv.y, acc.y);
        acc.z = fmaf(wgt, mv.z, acc.z);
        acc.w = fmaf(wgt, mv.w, acc.w);
        den += wgt;
    }
    float inv = 1.f / fmaxf(den, 1e-16f);
    float gx[4] = {acc.x * inv, acc.y * inv, acc.z * inv, acc.w * inv};
    #pragma unroll
    for (int c = 0; c < 4; c++)
        gx[c] = 0.5f * gx[c] * (1.f + erff(gx[c] * 0.70710678118654752f));
    float p[8];
    #pragma unroll
    for (int j = 0; j < 8; j++) p[j] = 0.f;
    #pragma unroll
    for (int c = 0; c < 4; c++) {
        #pragma unroll
        for (int j = 0; j < 8; j++)
            p[j] = fmaf(gx[c], d_Wfin[(lane * 4 + c) * 8 + j], p[j]);
    }
    #pragma unroll
    for (int off = 16; off > 0; off >>= 1)
        #pragma unroll
        for (int j = 0; j < 8; j++)
            p[j] += __shfl_xor_sync(0xffffffffu, p[j], off);
    if (lane == 0) {
        #pragma unroll
        for (int j = 0; j < 8; j++)
            out[w * 8 + j] = p[j] + d_preout[w * 8 + j] + d_bfin[j];
    }
}

// ---------------- launch ----------------
extern "C" void kernel_launch(void* const* d_in, const int* in_sizes, int n_in,
                              void* d_out, int out_size) {
    const float* x_movie = (const float*)d_in[0];
    const float* x_dir   = (const float*)d_in[1];
    const float* x_act   = (const float*)d_in[2];
    const int* src_dm = (const int*)d_in[3];
    const int* dst_dm = (const int*)d_in[4];
    const int* src_am = (const int*)d_in[5];
    const int* dst_am = (const int*)d_in[6];
    // d_in[7..10] dead (only movie output matters)
    const float* Wpre_m = (const float*)d_in[11];
    const float* Wpre_d = (const float*)d_in[12];
    const float* Wpre_a = (const float*)d_in[13];
    const float* bpre = (const float*)d_in[14];
    const float* Wk   = (const float*)d_in[15];
    const float* bk   = (const float*)d_in[16];
    const float* Wq   = (const float*)d_in[17];
    const float* bq   = (const float*)d_in[18];
    const float* Wv   = (const float*)d_in[19];
    const float* bv   = (const float*)d_in[20];
    const float* a_rel = (const float*)d_in[21];
    const float* m_rel = (const float*)d_in[22];
    const float* p_rel = (const float*)d_in[23];
    const float* skip  = (const float*)d_in[24];
    const float* Wa    = (const float*)d_in[25];
    const float* ba    = (const float*)d_in[26];
    const float* Wlin  = (const float*)d_in[27];
    const float* blin  = (const float*)d_in[28];
    float* out = (float*)d_out;

    const int smemG = 16 * 20 * 32 * 8;   // 81920 (movie fp16 W, max of the three)
    cudaFuncSetAttribute(gemm_all, cudaFuncAttributeMaxDynamicSharedMemorySize, smemG);

    phaseA_kernel<<<691, 256>>>(Wk, Wv, a_rel, m_rel, p_rel, Wpre_m, Wq, Wlin, skip, Wa);
    phaseB_kernel<<<654, 256>>>(Wpre_d, Wpre_a, bpre, bq, bk, bv, Wq, Wlin,
                                a_rel, m_rel, p_rel, skip, ba, blin,
                                src_dm, dst_dm, src_am, dst_am);
    gemm_all<<<666, 512, smemG>>>(x_movie, x_dir, x_act);
    agg_final<<<(NM * 32 + 255) / 256, 256>>>(out);
}